// round 8
// baseline (speedup 1.0000x reference)
#include <cuda_runtime.h>
#include <cuda_bf16.h>

#define BLK 256

// Persistent scratch: 4 accumulators + arrival counter.
// Zeroed at load; the finalizing CTA re-zeroes after draining, so every
// graph replay sees identical initial state.
__device__ float g_acc[4] = {0.f, 0.f, 0.f, 0.f};
__device__ unsigned int g_ticket = 0u;

__global__ void __launch_bounds__(BLK, 8) ccel_kernel(
    const float* __restrict__ input,
    const int* __restrict__ target,
    const float* __restrict__ X1,
    const int* __restrict__ Y1,
    const float* __restrict__ X2,
    const int* __restrict__ Y2,
    const float* __restrict__ T,
    float* __restrict__ out,
    int C, int B, float invB)
{
    const int tid  = threadIdx.x;
    const int n4   = C >> 2;
    const unsigned int ncta = gridDim.x;

    // Double-buffered per-warp partials: row parity p reads/writes ws[p];
    // with the single barrier per row this is provably race-free.
    __shared__ float ws[2][BLK / 32];

    int p = 0;
    for (int row = blockIdx.x; row < B; row += ncta, p ^= 1) {
        const size_t base = (size_t)row * (size_t)C;
        const float4* __restrict__ rp =
            reinterpret_cast<const float4*>(input + base);

        // Thread 0 issues the dependent gather chain first so its latency
        // overlaps this row's streaming loop.
        float xt = 0.f, xy1 = 0.f, xy2 = 0.f, x1v = 0.f, x2v = 0.f, t0 = 0.f;
        if (tid == 0) {
            int tgt = target[row];
            int y1  = Y1[tgt];
            int y2  = Y2[tgt];
            x1v = X1[tgt];
            x2v = X2[tgt];
            t0  = T[0];
            xt  = input[base + (size_t)tgt];
            xy1 = input[base + (size_t)y1];
            xy2 = input[base + (size_t)y2];
        }

        // One streaming pass: sum of exp(x) over the row. Simple strided
        // float4 loop; occupancy (8 CTAs/SM) supplies the MLP.
        float s = 0.0f;
        for (int i = tid; i < n4; i += BLK) {
            float4 v = __ldcs(rp + i);
            s += __expf(v.x);
            s += __expf(v.y);
            s += __expf(v.z);
            s += __expf(v.w);
        }

        #pragma unroll
        for (int o = 16; o; o >>= 1) s += __shfl_xor_sync(0xffffffffu, s, o);

        if ((tid & 31) == 0) ws[p][tid >> 5] = s;
        __syncthreads();

        if (tid == 0) {
            float S = 0.0f;
            #pragma unroll
            for (int w = 0; w < BLK / 32; w++) S += ws[p][w];

            float Et = __expf(xt);
            float E1 = __expf(xy1);
            float E2 = __expf(xy2);
            float num = t0 * (x1v * E1 + x2v * E2);   // corr * S
            bool  cond = Et > num;                    // p_t > corr (S > 0)
            float logS = __logf(S);

            // cond:  -log(p_t - corr) = logS - log(Et - num)
            // else:  -log(p_t)        = logS - xt
            float loss = cond ? (logS - __logf(Et - num)) : (logS - xt);

            float P1 = E1 / S;
            float P2 = E2 / S;
            bool  nz = (P1 != 0.0f) || (P2 != 0.0f);
            bool  k  = cond && nz;
            float z  = k ? (Et / num) : 0.0f;         // p_t / corr

            atomicAdd(&g_acc[0], loss * invB);
            atomicAdd(&g_acc[1], k ? 1.0f : 0.0f);
            atomicAdd(&g_acc[2], z);
            atomicAdd(&g_acc[3], cond ? 0.0f : 1.0f);
        }
        // No second barrier: ws[p] is only rewritten two rows later, after
        // the next barrier that thread 0 (the only reader) must also pass.
    }

    // Tail-only ordering: one fence per CTA, all during the drain phase —
    // never interleaved with the streaming loop (R5's regression).
    if (tid == 0) {
        __threadfence();
        unsigned int old = atomicInc(&g_ticket, ncta - 1u);
        if (old == ncta - 1u) {
            out[0] = atomicExch(&g_acc[0], 0.0f);
            out[1] = atomicExch(&g_acc[1], 0.0f);
            out[2] = atomicExch(&g_acc[2], 0.0f);
            out[3] = atomicExch(&g_acc[3], 0.0f);
        }
    }
}

extern "C" void kernel_launch(void* const* d_in, const int* in_sizes, int n_in,
                              void* d_out, int out_size) {
    const float* input  = (const float*)d_in[0];
    const int*   target = (const int*)d_in[1];
    const float* X1     = (const float*)d_in[2];
    const int*   Y1     = (const int*)d_in[3];
    const float* X2     = (const float*)d_in[4];
    const int*   Y2     = (const int*)d_in[5];
    const float* T      = (const float*)d_in[6];
    float* out = (float*)d_out;

    int B = in_sizes[1];          // target has B elements
    int C = in_sizes[2];          // X1 has C elements
    float invB = 1.0f / (float)B;

    int grid = 152 * 8;           // persistent: 8 CTAs per SM on GB300 (152 SMs)
    if (grid > B) grid = B;

    ccel_kernel<<<grid, BLK>>>(input, target, X1, Y1, X2, Y2, T, out,
                               C, B, invB);
}